// round 15
// baseline (speedup 1.0000x reference)
#include <cuda_runtime.h>
#include <cuda_fp16.h>
#include <cstdint>

// ─────────────── helpers ───────────────
__device__ __forceinline__ uint32_t smem_u32(const void* p) {
    uint32_t a;
    asm("{ .reg .u64 t; cvta.to.shared.u64 t, %1; cvt.u32.u64 %0, t; }"
        : "=r"(a) : "l"(p));
    return a;
}
#define CP_ASYNC16(dst, src) \
    asm volatile("cp.async.cg.shared.global [%0], [%1], 16;" :: "r"(dst), "l"(src) : "memory")
#define CP_COMMIT()  asm volatile("cp.async.commit_group;" ::: "memory")
#define CP_WAIT0()   asm volatile("cp.async.wait_group 0;" ::: "memory")

// fp16 tensor-core MMA (sm_80+): D(16x8) += A(16x16,row) * B(16x8,col), fp32 accum
#define MMA_FP16(d, a, b) \
    asm volatile("mma.sync.aligned.m16n8k16.row.col.f32.f16.f16.f32 " \
        "{%0,%1,%2,%3}, {%4,%5,%6,%7}, {%8,%9}, {%0,%1,%2,%3};" \
        : "+f"((d)[0]), "+f"((d)[1]), "+f"((d)[2]), "+f"((d)[3]) \
        : "r"((a)[0]), "r"((a)[1]), "r"((a)[2]), "r"((a)[3]), "r"((b)[0]), "r"((b)[1]))

// ─────────────── globals ───────────────
static __device__ float  g_c2[1024];
static __device__ int    g_maxcBits;
static __device__ float  g_accum[2];          // [0]=sum m*||z-q||^2, [1]=sum m
static __device__ int    g_fbCount;
static __device__ int    g_fbTok[32768];
static __device__ float  g_fbV[32768];
static __device__ int    g_fbIdx[32768 * 24];
static __device__ int    g_fb2Count;
static __device__ int    g_fb2Tok[32768];
static __device__ __half g_zh[32768 * 256];   // fp16 copy of z
static __device__ __half g_ch[1024 * 256];    // fp16 copy of codebook

__global__ void k_init() {
    g_accum[0] = 0.0f; g_accum[1] = 0.0f;
    g_maxcBits = 0; g_fbCount = 0; g_fb2Count = 0;
}

// fp32 -> fp16 pre-conversion (8 elems/thread, vectorized)
__global__ void k_prepz(const float4* __restrict__ z) {
    const size_t i = (size_t)blockIdx.x * 256 + threadIdx.x;   // 8 floats each
    float4 a = z[i * 2], b = z[i * 2 + 1];
    __half2 h0 = __floats2half2_rn(a.x, a.y);
    __half2 h1 = __floats2half2_rn(a.z, a.w);
    __half2 h2 = __floats2half2_rn(b.x, b.y);
    __half2 h3 = __floats2half2_rn(b.z, b.w);
    uint4 o;
    o.x = *(uint32_t*)&h0; o.y = *(uint32_t*)&h1;
    o.z = *(uint32_t*)&h2; o.w = *(uint32_t*)&h3;
    ((uint4*)g_zh)[i] = o;
}
__global__ void k_prepc(const float4* __restrict__ cb) {
    const size_t i = (size_t)blockIdx.x * 256 + threadIdx.x;
    float4 a = cb[i * 2], b = cb[i * 2 + 1];
    __half2 h0 = __floats2half2_rn(a.x, a.y);
    __half2 h1 = __floats2half2_rn(a.z, a.w);
    __half2 h2 = __floats2half2_rn(b.x, b.y);
    __half2 h3 = __floats2half2_rn(b.z, b.w);
    uint4 o;
    o.x = *(uint32_t*)&h0; o.y = *(uint32_t*)&h1;
    o.z = *(uint32_t*)&h2; o.w = *(uint32_t*)&h3;
    ((uint4*)g_ch)[i] = o;
}

__global__ void k_c2(const float4* __restrict__ cb) {
    int k    = blockIdx.x * 8 + (threadIdx.x >> 5);
    int lane = threadIdx.x & 31;
    float4 a = cb[(size_t)k * 64 + lane];
    float4 b = cb[(size_t)k * 64 + 32 + lane];
    float s = a.x*a.x + a.y*a.y + a.z*a.z + a.w*a.w
            + b.x*b.x + b.y*b.y + b.z*b.z + b.w*b.w;
    #pragma unroll
    for (int o = 16; o; o >>= 1) s += __shfl_down_sync(0xffffffffu, s, o);
    if (lane == 0) {
        g_c2[k] = s;
        atomicMax(&g_maxcBits, __float_as_int(sqrtf(s)));
    }
}

// ───── fused fp16 GEMM + in-register top-3 + certified select + STE epilogue ─────
// Tiles: 128 tokens x 128 codes per iter, K=256 in 8 chunks of 32 halves.
// smem row = 32 halves (64B) padded to 80B -> conflict-free frag loads.
static constexpr int ROW_B   = 80;                  // bytes per smem row
static constexpr int ROW_W   = 20;                  // 32-bit words per row
static constexpr int T_CHUNK = 128 * ROW_B;         // 10240 B per tile
static constexpr int OFF_A0 = 0;
static constexpr int OFF_A1 = T_CHUNK;
static constexpr int OFF_B0 = 2 * T_CHUNK;
static constexpr int OFF_B1 = 3 * T_CHUNK;
static constexpr int DYN_SMEM = 4 * T_CHUNK;        // 40960 B

extern __shared__ char dynsmem[];

__device__ __forceinline__ void fill_chunk(uint32_t sbase, int it, int mtile, int tid) {
    const int nt = it >> 3, kc = it & 7;
    const uint32_t bufA = sbase + ((it & 1) ? OFF_A1 : OFF_A0);
    const uint32_t bufB = sbase + ((it & 1) ? OFF_B1 : OFF_B0);
    const __half* zsrc = g_zh + (size_t)mtile * 128 * 256 + kc * 32;
    const __half* bsrc = g_ch + (size_t)nt    * 128 * 256 + kc * 32;
    // per tile: 128 rows x 32 halves = 512 16B units; 2 units per thread per tile
    #pragma unroll
    for (int i = 0; i < 2; i++) {
        int u = tid + i * 256, row = u >> 2, q = u & 3;
        CP_ASYNC16(bufA + row * ROW_B + q * 16, zsrc + (size_t)row * 256 + q * 8);
        CP_ASYNC16(bufB + row * ROW_B + q * 16, bsrc + (size_t)row * 256 + q * 8);
    }
}

__global__ void __launch_bounds__(256, 2) k_mma(const float* __restrict__ z,
                                                const float* __restrict__ mask,
                                                const float* __restrict__ cb,
                                                float* __restrict__ outQ,
                                                float* __restrict__ outIdx) {
    __shared__ float c2sh[1024];
    __shared__ float znsh[128];
    __shared__ int   idxsh[128];
    __shared__ float mks[128];
    __shared__ float lossP[8], maskP[8];

    const int tid  = threadIdx.x;
    const int wid  = tid >> 5;
    const int lane = tid & 31;
    const int g    = lane >> 2;
    const int tg   = lane & 3;
    const int mw   = wid >> 1;
    const int nw   = wid & 1;
    const int mtile = blockIdx.x;

    uint32_t sbase = smem_u32(dynsmem);
    const uint32_t* As[2] = { (const uint32_t*)(dynsmem + OFF_A0), (const uint32_t*)(dynsmem + OFF_A1) };
    const uint32_t* Bs[2] = { (const uint32_t*)(dynsmem + OFF_B0), (const uint32_t*)(dynsmem + OFF_B1) };

    #pragma unroll
    for (int i = 0; i < 4; i++) c2sh[tid + i * 256] = g_c2[tid + i * 256];

    float b1[4], b2[4], b3[4]; int i1[4], i2[4], i3[4];
    #pragma unroll
    for (int s = 0; s < 4; s++) {
        b1[s] = 3.0e38f; b2[s] = 3.0e38f; b3[s] = 3.0e38f;
        i1[s] = 0; i2[s] = 0; i3[s] = 0;
    }

    float acc[2][8][4];

    fill_chunk(sbase, 0, mtile, tid);
    CP_COMMIT();

    for (int it = 0; it < 64; it++) {
        const int p  = it & 1;
        const int kc = it & 7;
        const int nt = it >> 3;

        CP_WAIT0();
        __syncthreads();
        if (it + 1 < 64) { fill_chunk(sbase, it + 1, mtile, tid); CP_COMMIT(); }

        if (kc == 0) {
            #pragma unroll
            for (int mt = 0; mt < 2; mt++)
                #pragma unroll
                for (int ntl = 0; ntl < 8; ntl++)
                    #pragma unroll
                    for (int r = 0; r < 4; r++) acc[mt][ntl][r] = 0.0f;
        }

        const uint32_t* A = As[p];
        const uint32_t* B = Bs[p];
        // two K=16 steps cover the 32-half chunk
        #pragma unroll
        for (int ks = 0; ks < 2; ks++) {
            const int ka = ks * 8;           // 16 halves = 8 words
            uint32_t af[2][4], bf[8][2];
            #pragma unroll
            for (int mt = 0; mt < 2; mt++) {
                int r0 = mw * 32 + mt * 16 + g;
                af[mt][0] = A[r0 * ROW_W + ka + tg];
                af[mt][1] = A[(r0 + 8) * ROW_W + ka + tg];
                af[mt][2] = A[r0 * ROW_W + ka + tg + 4];
                af[mt][3] = A[(r0 + 8) * ROW_W + ka + tg + 4];
            }
            #pragma unroll
            for (int ntl = 0; ntl < 8; ntl++) {
                int c0 = nw * 64 + ntl * 8 + g;
                bf[ntl][0] = B[c0 * ROW_W + ka + tg];
                bf[ntl][1] = B[c0 * ROW_W + ka + tg + 4];
            }
            #pragma unroll
            for (int mt = 0; mt < 2; mt++)
                #pragma unroll
                for (int ntl = 0; ntl < 8; ntl++)
                    MMA_FP16(acc[mt][ntl], af[mt], bf[ntl]);
        }

        if (kc == 7) {
            #pragma unroll
            for (int mt = 0; mt < 2; mt++) {
                #pragma unroll
                for (int half = 0; half < 2; half++) {
                    const int slot = mt * 2 + half;
                    #pragma unroll
                    for (int ntl = 0; ntl < 8; ntl++) {
                        const int c0 = nt * 128 + nw * 64 + ntl * 8 + tg * 2;
                        #pragma unroll
                        for (int cc = 0; cc < 2; cc++) {
                            float s = fmaf(-2.0f, acc[mt][ntl][half * 2 + cc], c2sh[c0 + cc]);
                            if (s < b3[slot]) {
                                if (s < b2[slot]) {
                                    b3[slot] = b2[slot]; i3[slot] = i2[slot];
                                    if (s < b1[slot]) {
                                        b2[slot] = b1[slot]; i2[slot] = i1[slot];
                                        b1[slot] = s;        i1[slot] = c0 + cc;
                                    } else { b2[slot] = s; i2[slot] = c0 + cc; }
                                } else { b3[slot] = s; i3[slot] = c0 + cc; }
                            }
                        }
                    }
                }
            }
        }
    }

    // ───── fused epilogue (tier 1 only) ─────
    __syncthreads();                            // done reading A/B smem
    float* sS = (float*)dynsmem;                // [128][24] candidate scores
    int*   sI = (int*)(dynsmem + 128 * 24 * 4); // [128][24] candidate indices

    #pragma unroll
    for (int slot = 0; slot < 4; slot++) {
        const int row = mw * 32 + (slot >> 1) * 16 + (slot & 1) * 8 + g;
        const int col = (nw * 4 + tg) * 3;
        sS[row * 24 + col]     = b1[slot]; sI[row * 24 + col]     = i1[slot];
        sS[row * 24 + col + 1] = b2[slot]; sI[row * 24 + col + 1] = i2[slot];
        sS[row * 24 + col + 2] = b3[slot]; sI[row * 24 + col + 2] = i3[slot];
    }

    // phase 1: per-token ||z||^2 (warp per 16 tokens, coalesced)
    #pragma unroll 1
    for (int t = 0; t < 16; t++) {
        const int row = wid * 16 + t;
        const float4* z4 = (const float4*)(z + (size_t)(mtile * 128 + row) * 256) + lane * 2;
        float4 a0 = z4[0], a1 = z4[1];
        float s = a0.x*a0.x + a0.y*a0.y + a0.z*a0.z + a0.w*a0.w
                + a1.x*a1.x + a1.y*a1.y + a1.z*a1.z + a1.w*a1.w;
        #pragma unroll
        for (int o = 16; o; o >>= 1) s += __shfl_down_sync(0xffffffffu, s, o);
        if (lane == 0) znsh[row] = s;
    }
    __syncthreads();

    // phase 2: thread-per-token certificate
    if (tid < 128) {
        const int token = mtile * 128 + tid;
        const float m = mask[token];
        mks[tid] = m;
        float s1 = 3.0e38f, s2 = 3.0e38f, v = 3.0e38f;
        int idx1 = 0x7fffffff;
        #pragma unroll 4
        for (int j = 0; j < 24; j++) {
            float s = sS[tid * 24 + j];
            int   i = sI[tid * 24 + j];
            if (s < s1 || (s == s1 && i < idx1)) { s2 = s1; s1 = s; idx1 = i; }
            else s2 = fminf(s2, s);
            if ((j % 3) == 2) v = fminf(v, s);
        }
        const float maxc = __int_as_float(g_maxcBits);
        // fp16 conversion bound: rel product err <= 2^-10 (+slack)
        const float delta = 1.1e-3f * sqrtf(znsh[tid]) * maxc + 3e-2f;
        if (s2 - s1 > 2.0f * delta) {
            idxsh[tid] = idx1;
            outIdx[token] = (m > 0.0f) ? (float)idx1 : 0.0f;
        } else {
            idxsh[tid] = -1;
            int pos = atomicAdd(&g_fbCount, 1);
            g_fbTok[pos] = token;
            g_fbV[pos]   = v;
            #pragma unroll 4
            for (int j = 0; j < 24; j++) g_fbIdx[(size_t)pos * 24 + j] = sI[tid * 24 + j];
        }
    }
    __syncthreads();

    // phase 3: cooperative STE epilogue for certified tokens
    float lsum = 0.0f, msum = 0.0f;
    #pragma unroll 1
    for (int t = 0; t < 16; t++) {
        const int row = wid * 16 + t;
        const int idx = idxsh[row];
        if (idx < 0) continue;
        const int token = mtile * 128 + row;
        const float m = mks[row];
        const float4* z4 = (const float4*)(z  + (size_t)token * 256) + lane * 2;
        const float4* q4 = (const float4*)(cb + (size_t)idx   * 256) + lane * 2;
        float4 za = z4[0], zb = z4[1];
        float4 qa = q4[0], qb = q4[1];
        float ss = 0.0f;
        {
            float dx = za.x - qa.x, dy = za.y - qa.y, dz = za.z - qa.z, dw = za.w - qa.w;
            ss += dx*dx + dy*dy + dz*dz + dw*dw;
            dx = zb.x - qb.x; dy = zb.y - qb.y; dz = zb.z - qb.z; dw = zb.w - qb.w;
            ss += dx*dx + dy*dy + dz*dz + dw*dw;
        }
        float4* o4 = (float4*)(outQ + (size_t)token * 256) + lane * 2;
        float4 oa, ob;
        oa.x = (za.x + (qa.x - za.x)) * m; oa.y = (za.y + (qa.y - za.y)) * m;
        oa.z = (za.z + (qa.z - za.z)) * m; oa.w = (za.w + (qa.w - za.w)) * m;
        ob.x = (zb.x + (qb.x - zb.x)) * m; ob.y = (zb.y + (qb.y - zb.y)) * m;
        ob.z = (zb.z + (qb.z - zb.z)) * m; ob.w = (zb.w + (qb.w - zb.w)) * m;
        o4[0] = oa; o4[1] = ob;
        lsum += ss * m;
        if (lane == 0) msum += m;
    }
    #pragma unroll
    for (int o = 16; o; o >>= 1) lsum += __shfl_down_sync(0xffffffffu, lsum, o);
    if (lane == 0) { lossP[wid] = lsum; maskP[wid] = msum; }
    __syncthreads();
    if (tid == 0) {
        float a = 0.0f, b = 0.0f;
        #pragma unroll
        for (int w = 0; w < 8; w++) { a += lossP[w]; b += maskP[w]; }
        atomicAdd(&g_accum[0], a);
        atomicAdd(&g_accum[1], b);
    }
}

// ───── fb1: batched exact recheck of 24 candidates; unresolved -> fb2 list ─────
__global__ void k_fb1(const float* __restrict__ z,
                      const float* __restrict__ mask,
                      const float* __restrict__ cb,
                      float* __restrict__ outQ,
                      float* __restrict__ outIdx) {
    const int warp = threadIdx.x >> 5;
    const int lane = threadIdx.x & 31;
    const int wglobal = blockIdx.x * 8 + warp;
    const int nwarps  = gridDim.x * 8;
    const int count = g_fbCount;
    const float maxc = __int_as_float(g_maxcBits);

    for (int i = wglobal; i < count; i += nwarps) {
        const int token = g_fbTok[i];
        const float v   = g_fbV[i];

        const float4* z4 = (const float4*)(z + (size_t)token * 256) + lane * 2;
        const float4 za = z4[0], zb = z4[1];
        float zn = za.x*za.x + za.y*za.y + za.z*za.z + za.w*za.w
                 + zb.x*zb.x + zb.y*zb.y + zb.z*zb.z + zb.w*zb.w;
        #pragma unroll
        for (int o = 16; o; o >>= 1) zn += __shfl_xor_sync(0xffffffffu, zn, o);
        const float delta = 1.1e-3f * sqrtf(zn) * maxc + 3e-2f;

        float bS = 3.0e38f; int bI = 0x7fffffff;
        #pragma unroll 1
        for (int b = 0; b < 3; b++) {
            float d[8]; int ix[8];
            #pragma unroll
            for (int cc = 0; cc < 8; cc++) {
                ix[cc] = g_fbIdx[(size_t)i * 24 + b * 8 + cc];
                const float4* c4 = (const float4*)(cb + (size_t)ix[cc] * 256) + lane * 2;
                float4 xa = c4[0], xb = c4[1];
                d[cc] = za.x*xa.x + za.y*xa.y + za.z*xa.z + za.w*xa.w
                      + zb.x*xb.x + zb.y*xb.y + zb.z*xb.z + zb.w*xb.w;
            }
            #pragma unroll
            for (int o = 16; o; o >>= 1) {
                #pragma unroll
                for (int cc = 0; cc < 8; cc++)
                    d[cc] += __shfl_xor_sync(0xffffffffu, d[cc], o);
            }
            #pragma unroll
            for (int cc = 0; cc < 8; cc++) {
                float s = fmaf(-2.0f, d[cc], g_c2[ix[cc]]);
                if (s < bS || (s == bS && ix[cc] < bI)) { bS = s; bI = ix[cc]; }
            }
        }

        if (bS < v - delta) {
            const int idx = bI;
            const float m = mask[token];
            const float4* q4 = (const float4*)(cb + (size_t)idx * 256) + lane * 2;
            float4 qa = q4[0], qb = q4[1];
            float ss = 0.0f;
            {
                float dx = za.x - qa.x, dy = za.y - qa.y, dz = za.z - qa.z, dw = za.w - qa.w;
                ss += dx*dx + dy*dy + dz*dz + dw*dw;
                dx = zb.x - qb.x; dy = zb.y - qb.y; dz = zb.z - qb.z; dw = zb.w - qb.w;
                ss += dx*dx + dy*dy + dz*dz + dw*dw;
            }
            float4* o4 = (float4*)(outQ + (size_t)token * 256) + lane * 2;
            float4 oa, ob;
            oa.x = (za.x + (qa.x - za.x)) * m; oa.y = (za.y + (qa.y - za.y)) * m;
            oa.z = (za.z + (qa.z - za.z)) * m; oa.w = (za.w + (qa.w - za.w)) * m;
            ob.x = (zb.x + (qb.x - zb.x)) * m; ob.y = (zb.y + (qb.y - zb.y)) * m;
            ob.z = (zb.z + (qb.z - zb.z)) * m; ob.w = (zb.w + (qb.w - zb.w)) * m;
            o4[0] = oa; o4[1] = ob;
            #pragma unroll
            for (int o = 16; o; o >>= 1) ss += __shfl_down_sync(0xffffffffu, ss, o);
            if (lane == 0) {
                outIdx[token] = (m > 0.0f) ? (float)idx : 0.0f;
                atomicAdd(&g_accum[0], ss * m);
                atomicAdd(&g_accum[1], m);
            }
        } else if (lane == 0) {
            g_fb2Tok[atomicAdd(&g_fb2Count, 1)] = token;
        }
    }
}

// ───── fb2: block-per-token exact full scan over all 1024 codes ─────
__global__ void k_fb2(const float* __restrict__ z,
                      const float* __restrict__ mask,
                      const float* __restrict__ cb,
                      float* __restrict__ outQ,
                      float* __restrict__ outIdx) {
    __shared__ float wS[8];
    __shared__ int   wI[8];
    __shared__ int   sIdx;
    const int tid  = threadIdx.x;
    const int wid  = tid >> 5;
    const int lane = tid & 31;
    const int count = g_fb2Count;

    for (int t = blockIdx.x; t < count; t += gridDim.x) {
        const int token = g_fb2Tok[t];
        const float4* z4 = (const float4*)(z + (size_t)token * 256) + lane * 2;
        const float4 za = z4[0], zb = z4[1];

        float bS = 3.0e38f; int bI = 0x7fffffff;
        #pragma unroll 1
        for (int b = 0; b < 16; b++) {
            const int c0 = wid * 128 + b * 8;
            float d[8];
            #pragma unroll
            for (int cc = 0; cc < 8; cc++) {
                const float4* c4 = (const float4*)(cb + (size_t)(c0 + cc) * 256) + lane * 2;
                float4 xa = c4[0], xb = c4[1];
                d[cc] = za.x*xa.x + za.y*xa.y + za.z*xa.z + za.w*xa.w
                      + zb.x*xb.x + zb.y*xb.y + zb.z*xb.z + zb.w*xb.w;
            }
            #pragma unroll
            for (int o = 16; o; o >>= 1) {
                #pragma unroll
                for (int cc = 0; cc < 8; cc++)
                    d[cc] += __shfl_xor_sync(0xffffffffu, d[cc], o);
            }
            #pragma unroll
            for (int cc = 0; cc < 8; cc++) {
                float s = fmaf(-2.0f, d[cc], g_c2[c0 + cc]);
                if (s < bS || (s == bS && (c0 + cc) < bI)) { bS = s; bI = c0 + cc; }
            }
        }
        if (lane == 0) { wS[wid] = bS; wI[wid] = bI; }
        __syncthreads();
        if (tid == 0) {
            float fS = wS[0]; int fI = wI[0];
            #pragma unroll
            for (int w = 1; w < 8; w++)
                if (wS[w] < fS || (wS[w] == fS && wI[w] < fI)) { fS = wS[w]; fI = wI[w]; }
            sIdx = fI;
        }
        __syncthreads();

        if (wid == 0) {
            const int idx = sIdx;
            const float m = mask[token];
            const float4* q4 = (const float4*)(cb + (size_t)idx * 256) + lane * 2;
            float4 qa = q4[0], qb = q4[1];
            float ss = 0.0f;
            {
                float dx = za.x - qa.x, dy = za.y - qa.y, dz = za.z - qa.z, dw = za.w - qa.w;
                ss += dx*dx + dy*dy + dz*dz + dw*dw;
                dx = zb.x - qb.x; dy = zb.y - qb.y; dz = zb.z - qb.z; dw = zb.w - qb.w;
                ss += dx*dx + dy*dy + dz*dz + dw*dw;
            }
            float4* o4 = (float4*)(outQ + (size_t)token * 256) + lane * 2;
            float4 oa, ob;
            oa.x = (za.x + (qa.x - za.x)) * m; oa.y = (za.y + (qa.y - za.y)) * m;
            oa.z = (za.z + (qa.z - za.z)) * m; oa.w = (za.w + (qa.w - za.w)) * m;
            ob.x = (zb.x + (qb.x - zb.x)) * m; ob.y = (zb.y + (qb.y - zb.y)) * m;
            ob.z = (zb.z + (qb.z - zb.z)) * m; ob.w = (zb.w + (qb.w - zb.w)) * m;
            o4[0] = oa; o4[1] = ob;
            #pragma unroll
            for (int o = 16; o; o >>= 1) ss += __shfl_down_sync(0xffffffffu, ss, o);
            if (lane == 0) {
                outIdx[token] = (m > 0.0f) ? (float)idx : 0.0f;
                atomicAdd(&g_accum[0], ss * m);
                atomicAdd(&g_accum[1], m);
            }
        }
        __syncthreads();
    }
}

__global__ void k_finalize(float* outLoss) {
    outLoss[0] = 0.25f * (g_accum[0] / (g_accum[1] * 256.0f));
}

// ─────────────── launcher ───────────────
extern "C" void kernel_launch(void* const* d_in, const int* in_sizes, int n_in,
                              void* d_out, int out_size) {
    const float* z    = (const float*)d_in[0];   // (B,S,D)
    const float* mask = (const float*)d_in[1];   // (B,S)
    const float* cb   = (const float*)d_in[2];   // (K,D)

    const int BSD = in_sizes[0];                 // 8388608
    const int N   = in_sizes[1];                 // 32768

    float* out     = (float*)d_out;
    float* outQ    = out;
    float* outLoss = out + BSD;
    float* outIdx  = out + BSD + 1;

    cudaFuncSetAttribute(k_mma, cudaFuncAttributeMaxDynamicSharedMemorySize, DYN_SMEM);

    k_init<<<1, 1>>>();
    k_prepz<<<BSD / (256 * 8), 256>>>((const float4*)z);     // 4096 blocks
    k_prepc<<<128, 256>>>((const float4*)cb);
    k_c2<<<128, 256>>>((const float4*)cb);
    k_mma<<<N / 128, 256, DYN_SMEM>>>(z, mask, cb, outQ, outIdx);
    k_fb1<<<512, 256>>>(z, mask, cb, outQ, outIdx);
    k_fb2<<<192, 256>>>(z, mask, cb, outQ, outIdx);
    k_finalize<<<1, 1>>>(outLoss);
}

// round 16
// speedup vs baseline: 1.8216x; 1.8216x over previous
#include <cuda_runtime.h>
#include <cuda_fp16.h>
#include <cstdint>

// ─────────────── helpers ───────────────
__device__ __forceinline__ uint32_t smem_u32(const void* p) {
    uint32_t a;
    asm("{ .reg .u64 t; cvta.to.shared.u64 t, %1; cvt.u32.u64 %0, t; }"
        : "=r"(a) : "l"(p));
    return a;
}
#define CP_ASYNC16(dst, src) \
    asm volatile("cp.async.cg.shared.global [%0], [%1], 16;" :: "r"(dst), "l"(src) : "memory")
#define CP_COMMIT()  asm volatile("cp.async.commit_group;" ::: "memory")
#define CP_WAIT0()   asm volatile("cp.async.wait_group 0;" ::: "memory")

#define LDMATRIX_X4(r0, r1, r2, r3, addr) \
    asm volatile("ldmatrix.sync.aligned.m8n8.x4.shared.b16 {%0,%1,%2,%3}, [%4];" \
        : "=r"(r0), "=r"(r1), "=r"(r2), "=r"(r3) : "r"(addr))

// fp16 tensor-core MMA (sm_80+): D(16x8) += A(16x16,row) * B(16x8,col), fp32 accum
#define MMA_FP16(d, a, b) \
    asm volatile("mma.sync.aligned.m16n8k16.row.col.f32.f16.f16.f32 " \
        "{%0,%1,%2,%3}, {%4,%5,%6,%7}, {%8,%9}, {%0,%1,%2,%3};" \
        : "+f"((d)[0]), "+f"((d)[1]), "+f"((d)[2]), "+f"((d)[3]) \
        : "r"((a)[0]), "r"((a)[1]), "r"((a)[2]), "r"((a)[3]), "r"((b)[0]), "r"((b)[1]))

// ─────────────── globals ───────────────
static __device__ float  g_c2[1024];
static __device__ int    g_maxcBits;
static __device__ float  g_accum[2];          // [0]=sum m*||z-q||^2, [1]=sum m
static __device__ int    g_fbCount;
static __device__ int    g_fbTok[32768];
static __device__ float  g_fbV[32768];
static __device__ int    g_fbIdx[32768 * 24];
static __device__ int    g_fb2Count;
static __device__ int    g_fb2Tok[32768];
static __device__ __half g_zh[32768 * 256];   // fp16 copy of z
static __device__ __half g_ch[1024 * 256];    // fp16 copy of codebook

__global__ void k_init() {
    g_accum[0] = 0.0f; g_accum[1] = 0.0f;
    g_maxcBits = 0; g_fbCount = 0; g_fb2Count = 0;
}

// fp32 -> fp16 pre-conversion (8 elems/thread, vectorized)
__global__ void k_prepz(const float4* __restrict__ z) {
    const size_t i = (size_t)blockIdx.x * 256 + threadIdx.x;
    float4 a = z[i * 2], b = z[i * 2 + 1];
    __half2 h0 = __floats2half2_rn(a.x, a.y);
    __half2 h1 = __floats2half2_rn(a.z, a.w);
    __half2 h2 = __floats2half2_rn(b.x, b.y);
    __half2 h3 = __floats2half2_rn(b.z, b.w);
    uint4 o;
    o.x = *(uint32_t*)&h0; o.y = *(uint32_t*)&h1;
    o.z = *(uint32_t*)&h2; o.w = *(uint32_t*)&h3;
    ((uint4*)g_zh)[i] = o;
}
__global__ void k_prepc(const float4* __restrict__ cb) {
    const size_t i = (size_t)blockIdx.x * 256 + threadIdx.x;
    float4 a = cb[i * 2], b = cb[i * 2 + 1];
    __half2 h0 = __floats2half2_rn(a.x, a.y);
    __half2 h1 = __floats2half2_rn(a.z, a.w);
    __half2 h2 = __floats2half2_rn(b.x, b.y);
    __half2 h3 = __floats2half2_rn(b.z, b.w);
    uint4 o;
    o.x = *(uint32_t*)&h0; o.y = *(uint32_t*)&h1;
    o.z = *(uint32_t*)&h2; o.w = *(uint32_t*)&h3;
    ((uint4*)g_ch)[i] = o;
}

__global__ void k_c2(const float4* __restrict__ cb) {
    int k    = blockIdx.x * 8 + (threadIdx.x >> 5);
    int lane = threadIdx.x & 31;
    float4 a = cb[(size_t)k * 64 + lane];
    float4 b = cb[(size_t)k * 64 + 32 + lane];
    float s = a.x*a.x + a.y*a.y + a.z*a.z + a.w*a.w
            + b.x*b.x + b.y*b.y + b.z*b.z + b.w*b.w;
    #pragma unroll
    for (int o = 16; o; o >>= 1) s += __shfl_down_sync(0xffffffffu, s, o);
    if (lane == 0) {
        g_c2[k] = s;
        atomicMax(&g_maxcBits, __float_as_int(sqrtf(s)));
    }
}

// ───── fused fp16 GEMM (ldmatrix) + top-3 + certified select + STE epilogue ─────
// Tiles: 128 tokens x 128 codes; K=256 in 4 chunks of 64 halves (32 iters total).
// smem row = 64 halves (128B) padded to 144B; ldmatrix rows hit banks 4r mod 32.
static constexpr int ROW_B   = 144;                 // bytes per smem row
static constexpr int T_CHUNK = 128 * ROW_B;         // 18432 B per tile
static constexpr int OFF_A0 = 0;
static constexpr int OFF_A1 = T_CHUNK;
static constexpr int OFF_B0 = 2 * T_CHUNK;
static constexpr int OFF_B1 = 3 * T_CHUNK;
static constexpr int DYN_SMEM = 4 * T_CHUNK;        // 73728 B -> 2 CTAs/SM

extern __shared__ char dynsmem[];

__device__ __forceinline__ void fill_chunk(uint32_t sbase, int it, int mtile, int tid) {
    const int nt = it >> 2, kc = it & 3;
    const uint32_t bufA = sbase + ((it & 1) ? OFF_A1 : OFF_A0);
    const uint32_t bufB = sbase + ((it & 1) ? OFF_B1 : OFF_B0);
    const __half* zsrc = g_zh + (size_t)mtile * 128 * 256 + kc * 64;
    const __half* bsrc = g_ch + (size_t)nt    * 128 * 256 + kc * 64;
    // per tile: 128 rows x 64 halves = 1024 16B units; 4 units/thread/tile
    #pragma unroll
    for (int i = 0; i < 4; i++) {
        int u = tid + i * 256, row = u >> 3, q = u & 7;
        CP_ASYNC16(bufA + row * ROW_B + q * 16, zsrc + (size_t)row * 256 + q * 8);
        CP_ASYNC16(bufB + row * ROW_B + q * 16, bsrc + (size_t)row * 256 + q * 8);
    }
}

__global__ void __launch_bounds__(256, 2) k_mma(const float* __restrict__ z,
                                                const float* __restrict__ mask,
                                                const float* __restrict__ cb,
                                                float* __restrict__ outQ,
                                                float* __restrict__ outIdx) {
    __shared__ float c2sh[1024];
    __shared__ float znsh[128];
    __shared__ int   idxsh[128];
    __shared__ float mks[128];
    __shared__ float lossP[8], maskP[8];

    const int tid  = threadIdx.x;
    const int wid  = tid >> 5;
    const int lane = tid & 31;
    const int g    = lane >> 2;
    const int tg   = lane & 3;
    const int mw   = wid >> 1;
    const int nw   = wid & 1;
    const int mtile = blockIdx.x;

    uint32_t sbase = smem_u32(dynsmem);

    // ldmatrix per-lane address offsets (bytes), constant across iterations
    const int sub = lane >> 3, rr = lane & 7;
    uint32_t aoff[2], boff[4];
    #pragma unroll
    for (int mt = 0; mt < 2; mt++)
        aoff[mt] = (uint32_t)((mw * 32 + mt * 16 + (sub & 1) * 8 + rr) * ROW_B
                              + (sub >> 1) * 16);
    #pragma unroll
    for (int p2 = 0; p2 < 4; p2++)
        boff[p2] = (uint32_t)((nw * 64 + p2 * 16 + (sub >> 1) * 8 + rr) * ROW_B
                              + (sub & 1) * 16);

    #pragma unroll
    for (int i = 0; i < 4; i++) c2sh[tid + i * 256] = g_c2[tid + i * 256];

    float b1[4], b2[4], b3[4]; int i1[4], i2[4], i3[4];
    #pragma unroll
    for (int s = 0; s < 4; s++) {
        b1[s] = 3.0e38f; b2[s] = 3.0e38f; b3[s] = 3.0e38f;
        i1[s] = 0; i2[s] = 0; i3[s] = 0;
    }

    float acc[2][8][4];

    fill_chunk(sbase, 0, mtile, tid);
    CP_COMMIT();

    for (int it = 0; it < 32; it++) {
        const int kc = it & 3;
        const int nt = it >> 2;
        const uint32_t bufA = sbase + ((it & 1) ? OFF_A1 : OFF_A0);
        const uint32_t bufB = sbase + ((it & 1) ? OFF_B1 : OFF_B0);

        CP_WAIT0();
        __syncthreads();
        if (it + 1 < 32) { fill_chunk(sbase, it + 1, mtile, tid); CP_COMMIT(); }

        if (kc == 0) {
            #pragma unroll
            for (int mt = 0; mt < 2; mt++)
                #pragma unroll
                for (int ntl = 0; ntl < 8; ntl++)
                    #pragma unroll
                    for (int r = 0; r < 4; r++) acc[mt][ntl][r] = 0.0f;
        }

        // 4 K=16 steps cover the 64-half chunk
        #pragma unroll
        for (int ks = 0; ks < 4; ks++) {
            const uint32_t kb = ks * 32;     // 16 halves = 32 bytes
            uint32_t af[2][4], bf[8][2];
            #pragma unroll
            for (int mt = 0; mt < 2; mt++)
                LDMATRIX_X4(af[mt][0], af[mt][1], af[mt][2], af[mt][3],
                            bufA + aoff[mt] + kb);
            #pragma unroll
            for (int p2 = 0; p2 < 4; p2++)
                LDMATRIX_X4(bf[2 * p2][0], bf[2 * p2][1],
                            bf[2 * p2 + 1][0], bf[2 * p2 + 1][1],
                            bufB + boff[p2] + kb);
            #pragma unroll
            for (int mt = 0; mt < 2; mt++)
                #pragma unroll
                for (int ntl = 0; ntl < 8; ntl++)
                    MMA_FP16(acc[mt][ntl], af[mt], bf[ntl]);
        }

        if (kc == 3) {
            #pragma unroll
            for (int mt = 0; mt < 2; mt++) {
                #pragma unroll
                for (int half = 0; half < 2; half++) {
                    const int slot = mt * 2 + half;
                    #pragma unroll
                    for (int ntl = 0; ntl < 8; ntl++) {
                        const int c0 = nt * 128 + nw * 64 + ntl * 8 + tg * 2;
                        #pragma unroll
                        for (int cc = 0; cc < 2; cc++) {
                            float s = fmaf(-2.0f, acc[mt][ntl][half * 2 + cc], c2sh[c0 + cc]);
                            if (s < b3[slot]) {
                                if (s < b2[slot]) {
                                    b3[slot] = b2[slot]; i3[slot] = i2[slot];
                                    if (s < b1[slot]) {
                                        b2[slot] = b1[slot]; i2[slot] = i1[slot];
                                        b1[slot] = s;        i1[slot] = c0 + cc;
                                    } else { b2[slot] = s; i2[slot] = c0 + cc; }
                                } else { b3[slot] = s; i3[slot] = c0 + cc; }
                            }
                        }
                    }
                }
            }
        }
    }

    // ───── fused epilogue (tier 1 only) ─────
    __syncthreads();
    float* sS = (float*)dynsmem;                // [128][24] candidate scores
    int*   sI = (int*)(dynsmem + 128 * 24 * 4); // [128][24] candidate indices

    #pragma unroll
    for (int slot = 0; slot < 4; slot++) {
        const int row = mw * 32 + (slot >> 1) * 16 + (slot & 1) * 8 + g;
        const int col = (nw * 4 + tg) * 3;
        sS[row * 24 + col]     = b1[slot]; sI[row * 24 + col]     = i1[slot];
        sS[row * 24 + col + 1] = b2[slot]; sI[row * 24 + col + 1] = i2[slot];
        sS[row * 24 + col + 2] = b3[slot]; sI[row * 24 + col + 2] = i3[slot];
    }

    // per-token ||z||^2
    #pragma unroll 1
    for (int t = 0; t < 16; t++) {
        const int row = wid * 16 + t;
        const float4* z4 = (const float4*)(z + (size_t)(mtile * 128 + row) * 256) + lane * 2;
        float4 a0 = z4[0], a1 = z4[1];
        float s = a0.x*a0.x + a0.y*a0.y + a0.z*a0.z + a0.w*a0.w
                + a1.x*a1.x + a1.y*a1.y + a1.z*a1.z + a1.w*a1.w;
        #pragma unroll
        for (int o = 16; o; o >>= 1) s += __shfl_down_sync(0xffffffffu, s, o);
        if (lane == 0) znsh[row] = s;
    }
    __syncthreads();

    // thread-per-token certificate
    if (tid < 128) {
        const int token = mtile * 128 + tid;
        const float m = mask[token];
        mks[tid] = m;
        float s1 = 3.0e38f, s2 = 3.0e38f, v = 3.0e38f;
        int idx1 = 0x7fffffff;
        #pragma unroll 4
        for (int j = 0; j < 24; j++) {
            float s = sS[tid * 24 + j];
            int   i = sI[tid * 24 + j];
            if (s < s1 || (s == s1 && i < idx1)) { s2 = s1; s1 = s; idx1 = i; }
            else s2 = fminf(s2, s);
            if ((j % 3) == 2) v = fminf(v, s);
        }
        const float maxc = __int_as_float(g_maxcBits);
        const float delta = 1.1e-3f * sqrtf(znsh[tid]) * maxc + 3e-2f;
        if (s2 - s1 > 2.0f * delta) {
            idxsh[tid] = idx1;
            outIdx[token] = (m > 0.0f) ? (float)idx1 : 0.0f;
        } else {
            idxsh[tid] = -1;
            int pos = atomicAdd(&g_fbCount, 1);
            g_fbTok[pos] = token;
            g_fbV[pos]   = v;
            #pragma unroll 4
            for (int j = 0; j < 24; j++) g_fbIdx[(size_t)pos * 24 + j] = sI[tid * 24 + j];
        }
    }
    __syncthreads();

    // cooperative STE epilogue for certified tokens
    float lsum = 0.0f, msum = 0.0f;
    #pragma unroll 1
    for (int t = 0; t < 16; t++) {
        const int row = wid * 16 + t;
        const int idx = idxsh[row];
        if (idx < 0) continue;
        const int token = mtile * 128 + row;
        const float m = mks[row];
        const float4* z4 = (const float4*)(z  + (size_t)token * 256) + lane * 2;
        const float4* q4 = (const float4*)(cb + (size_t)idx   * 256) + lane * 2;
        float4 za = z4[0], zb = z4[1];
        float4 qa = q4[0], qb = q4[1];
        float ss = 0.0f;
        {
            float dx = za.x - qa.x, dy = za.y - qa.y, dz = za.z - qa.z, dw = za.w - qa.w;
            ss += dx*dx + dy*dy + dz*dz + dw*dw;
            dx = zb.x - qb.x; dy = zb.y - qb.y; dz = zb.z - qb.z; dw = zb.w - qb.w;
            ss += dx*dx + dy*dy + dz*dz + dw*dw;
        }
        float4* o4 = (float4*)(outQ + (size_t)token * 256) + lane * 2;
        float4 oa, ob;
        oa.x = (za.x + (qa.x - za.x)) * m; oa.y = (za.y + (qa.y - za.y)) * m;
        oa.z = (za.z + (qa.z - za.z)) * m; oa.w = (za.w + (qa.w - za.w)) * m;
        ob.x = (zb.x + (qb.x - zb.x)) * m; ob.y = (zb.y + (qb.y - zb.y)) * m;
        ob.z = (zb.z + (qb.z - zb.z)) * m; ob.w = (zb.w + (qb.w - zb.w)) * m;
        o4[0] = oa; o4[1] = ob;
        lsum += ss * m;
        if (lane == 0) msum += m;
    }
    #pragma unroll
    for (int o = 16; o; o >>= 1) lsum += __shfl_down_sync(0xffffffffu, lsum, o);
    if (lane == 0) { lossP[wid] = lsum; maskP[wid] = msum; }
    __syncthreads();
    if (tid == 0) {
        float a = 0.0f, b = 0.0f;
        #pragma unroll
        for (int w = 0; w < 8; w++) { a += lossP[w]; b += maskP[w]; }
        atomicAdd(&g_accum[0], a);
        atomicAdd(&g_accum[1], b);
    }
}

// ───── fb1: batched exact recheck of 24 candidates; unresolved -> fb2 list ─────
__global__ void k_fb1(const float* __restrict__ z,
                      const float* __restrict__ mask,
                      const float* __restrict__ cb,
                      float* __restrict__ outQ,
                      float* __restrict__ outIdx) {
    const int warp = threadIdx.x >> 5;
    const int lane = threadIdx.x & 31;
    const int wglobal = blockIdx.x * 8 + warp;
    const int nwarps  = gridDim.x * 8;
    const int count = g_fbCount;
    const float maxc = __int_as_float(g_maxcBits);

    for (int i = wglobal; i < count; i += nwarps) {
        const int token = g_fbTok[i];
        const float v   = g_fbV[i];

        const float4* z4 = (const float4*)(z + (size_t)token * 256) + lane * 2;
        const float4 za = z4[0], zb = z4[1];
        float zn = za.x*za.x + za.y*za.y + za.z*za.z + za.w*za.w
                 + zb.x*zb.x + zb.y*zb.y + zb.z*zb.z + zb.w*zb.w;
        #pragma unroll
        for (int o = 16; o; o >>= 1) zn += __shfl_xor_sync(0xffffffffu, zn, o);
        const float delta = 1.1e-3f * sqrtf(zn) * maxc + 3e-2f;

        float bS = 3.0e38f; int bI = 0x7fffffff;
        #pragma unroll 1
        for (int b = 0; b < 3; b++) {
            float d[8]; int ix[8];
            #pragma unroll
            for (int cc = 0; cc < 8; cc++) {
                ix[cc] = g_fbIdx[(size_t)i * 24 + b * 8 + cc];
                const float4* c4 = (const float4*)(cb + (size_t)ix[cc] * 256) + lane * 2;
                float4 xa = c4[0], xb = c4[1];
                d[cc] = za.x*xa.x + za.y*xa.y + za.z*xa.z + za.w*xa.w
                      + zb.x*xb.x + zb.y*xb.y + zb.z*xb.z + zb.w*xb.w;
            }
            #pragma unroll
            for (int o = 16; o; o >>= 1) {
                #pragma unroll
                for (int cc = 0; cc < 8; cc++)
                    d[cc] += __shfl_xor_sync(0xffffffffu, d[cc], o);
            }
            #pragma unroll
            for (int cc = 0; cc < 8; cc++) {
                float s = fmaf(-2.0f, d[cc], g_c2[ix[cc]]);
                if (s < bS || (s == bS && ix[cc] < bI)) { bS = s; bI = ix[cc]; }
            }
        }

        if (bS < v - delta) {
            const int idx = bI;
            const float m = mask[token];
            const float4* q4 = (const float4*)(cb + (size_t)idx * 256) + lane * 2;
            float4 qa = q4[0], qb = q4[1];
            float ss = 0.0f;
            {
                float dx = za.x - qa.x, dy = za.y - qa.y, dz = za.z - qa.z, dw = za.w - qa.w;
                ss += dx*dx + dy*dy + dz*dz + dw*dw;
                dx = zb.x - qb.x; dy = zb.y - qb.y; dz = zb.z - qb.z; dw = zb.w - qb.w;
                ss += dx*dx + dy*dy + dz*dz + dw*dw;
            }
            float4* o4 = (float4*)(outQ + (size_t)token * 256) + lane * 2;
            float4 oa, ob;
            oa.x = (za.x + (qa.x - za.x)) * m; oa.y = (za.y + (qa.y - za.y)) * m;
            oa.z = (za.z + (qa.z - za.z)) * m; oa.w = (za.w + (qa.w - za.w)) * m;
            ob.x = (zb.x + (qb.x - zb.x)) * m; ob.y = (zb.y + (qb.y - zb.y)) * m;
            ob.z = (zb.z + (qb.z - zb.z)) * m; ob.w = (zb.w + (qb.w - zb.w)) * m;
            o4[0] = oa; o4[1] = ob;
            #pragma unroll
            for (int o = 16; o; o >>= 1) ss += __shfl_down_sync(0xffffffffu, ss, o);
            if (lane == 0) {
                outIdx[token] = (m > 0.0f) ? (float)idx : 0.0f;
                atomicAdd(&g_accum[0], ss * m);
                atomicAdd(&g_accum[1], m);
            }
        } else if (lane == 0) {
            g_fb2Tok[atomicAdd(&g_fb2Count, 1)] = token;
        }
    }
}

// ───── fb2: block-per-token exact full scan over all 1024 codes ─────
__global__ void k_fb2(const float* __restrict__ z,
                      const float* __restrict__ mask,
                      const float* __restrict__ cb,
                      float* __restrict__ outQ,
                      float* __restrict__ outIdx) {
    __shared__ float wS[8];
    __shared__ int   wI[8];
    __shared__ int   sIdx;
    const int tid  = threadIdx.x;
    const int wid  = tid >> 5;
    const int lane = tid & 31;
    const int count = g_fb2Count;

    for (int t = blockIdx.x; t < count; t += gridDim.x) {
        const int token = g_fb2Tok[t];
        const float4* z4 = (const float4*)(z + (size_t)token * 256) + lane * 2;
        const float4 za = z4[0], zb = z4[1];

        float bS = 3.0e38f; int bI = 0x7fffffff;
        #pragma unroll 1
        for (int b = 0; b < 16; b++) {
            const int c0 = wid * 128 + b * 8;
            float d[8];
            #pragma unroll
            for (int cc = 0; cc < 8; cc++) {
                const float4* c4 = (const float4*)(cb + (size_t)(c0 + cc) * 256) + lane * 2;
                float4 xa = c4[0], xb = c4[1];
                d[cc] = za.x*xa.x + za.y*xa.y + za.z*xa.z + za.w*xa.w
                      + zb.x*xb.x + zb.y*xb.y + zb.z*xb.z + zb.w*xb.w;
            }
            #pragma unroll
            for (int o = 16; o; o >>= 1) {
                #pragma unroll
                for (int cc = 0; cc < 8; cc++)
                    d[cc] += __shfl_xor_sync(0xffffffffu, d[cc], o);
            }
            #pragma unroll
            for (int cc = 0; cc < 8; cc++) {
                float s = fmaf(-2.0f, d[cc], g_c2[c0 + cc]);
                if (s < bS || (s == bS && (c0 + cc) < bI)) { bS = s; bI = c0 + cc; }
            }
        }
        if (lane == 0) { wS[wid] = bS; wI[wid] = bI; }
        __syncthreads();
        if (tid == 0) {
            float fS = wS[0]; int fI = wI[0];
            #pragma unroll
            for (int w = 1; w < 8; w++)
                if (wS[w] < fS || (wS[w] == fS && wI[w] < fI)) { fS = wS[w]; fI = wI[w]; }
            sIdx = fI;
        }
        __syncthreads();

        if (wid == 0) {
            const int idx = sIdx;
            const float m = mask[token];
            const float4* q4 = (const float4*)(cb + (size_t)idx * 256) + lane * 2;
            float4 qa = q4[0], qb = q4[1];
            float ss = 0.0f;
            {
                float dx = za.x - qa.x, dy = za.y - qa.y, dz = za.z - qa.z, dw = za.w - qa.w;
                ss += dx*dx + dy*dy + dz*dz + dw*dw;
                dx = zb.x - qb.x; dy = zb.y - qb.y; dz = zb.z - qb.z; dw = zb.w - qb.w;
                ss += dx*dx + dy*dy + dz*dz + dw*dw;
            }
            float4* o4 = (float4*)(outQ + (size_t)token * 256) + lane * 2;
            float4 oa, ob;
            oa.x = (za.x + (qa.x - za.x)) * m; oa.y = (za.y + (qa.y - za.y)) * m;
            oa.z = (za.z + (qa.z - za.z)) * m; oa.w = (za.w + (qa.w - za.w)) * m;
            ob.x = (zb.x + (qb.x - zb.x)) * m; ob.y = (zb.y + (qb.y - zb.y)) * m;
            ob.z = (zb.z + (qb.z - zb.z)) * m; ob.w = (zb.w + (qb.w - zb.w)) * m;
            o4[0] = oa; o4[1] = ob;
            #pragma unroll
            for (int o = 16; o; o >>= 1) ss += __shfl_down_sync(0xffffffffu, ss, o);
            if (lane == 0) {
                outIdx[token] = (m > 0.0f) ? (float)idx : 0.0f;
                atomicAdd(&g_accum[0], ss * m);
                atomicAdd(&g_accum[1], m);
            }
        }
        __syncthreads();
    }
}

__global__ void k_finalize(float* outLoss) {
    outLoss[0] = 0.25f * (g_accum[0] / (g_accum[1] * 256.0f));
}

// ─────────────── launcher ───────────────
extern "C" void kernel_launch(void* const* d_in, const int* in_sizes, int n_in,
                              void* d_out, int out_size) {
    const float* z    = (const float*)d_in[0];   // (B,S,D)
    const float* mask = (const float*)d_in[1];   // (B,S)
    const float* cb   = (const float*)d_in[2];   // (K,D)

    const int BSD = in_sizes[0];                 // 8388608
    const int N   = in_sizes[1];                 // 32768

    float* out     = (float*)d_out;
    float* outQ    = out;
    float* outLoss = out + BSD;
    float* outIdx  = out + BSD + 1;

    cudaFuncSetAttribute(k_mma, cudaFuncAttributeMaxDynamicSharedMemorySize, DYN_SMEM);

    k_init<<<1, 1>>>();
    k_prepz<<<BSD / (256 * 8), 256>>>((const float4*)z);
    k_prepc<<<128, 256>>>((const float4*)cb);
    k_c2<<<128, 256>>>((const float4*)cb);
    k_mma<<<N / 128, 256, DYN_SMEM>>>(z, mask, cb, outQ, outIdx);
    k_fb1<<<512, 256>>>(z, mask, cb, outQ, outIdx);
    k_fb2<<<192, 256>>>(z, mask, cb, outQ, outIdx);
    k_finalize<<<1, 1>>>(outLoss);
}

// round 17
// speedup vs baseline: 1.9085x; 1.0477x over previous
#include <cuda_runtime.h>
#include <cuda_fp16.h>
#include <cstdint>

// ─────────────── helpers ───────────────
__device__ __forceinline__ uint32_t smem_u32(const void* p) {
    uint32_t a;
    asm("{ .reg .u64 t; cvta.to.shared.u64 t, %1; cvt.u32.u64 %0, t; }"
        : "=r"(a) : "l"(p));
    return a;
}
#define CP_ASYNC16(dst, src) \
    asm volatile("cp.async.cg.shared.global [%0], [%1], 16;" :: "r"(dst), "l"(src) : "memory")
#define CP_COMMIT()  asm volatile("cp.async.commit_group;" ::: "memory")
#define CP_WAIT0()   asm volatile("cp.async.wait_group 0;" ::: "memory")

#define LDMATRIX_X4(r0, r1, r2, r3, addr) \
    asm volatile("ldmatrix.sync.aligned.m8n8.x4.shared.b16 {%0,%1,%2,%3}, [%4];" \
        : "=r"(r0), "=r"(r1), "=r"(r2), "=r"(r3) : "r"(addr))

// fp16 tensor-core MMA (sm_80+): D(16x8) += A(16x16,row) * B(16x8,col), fp32 accum
#define MMA_FP16(d, a, b) \
    asm volatile("mma.sync.aligned.m16n8k16.row.col.f32.f16.f16.f32 " \
        "{%0,%1,%2,%3}, {%4,%5,%6,%7}, {%8,%9}, {%0,%1,%2,%3};" \
        : "+f"((d)[0]), "+f"((d)[1]), "+f"((d)[2]), "+f"((d)[3]) \
        : "r"((a)[0]), "r"((a)[1]), "r"((a)[2]), "r"((a)[3]), "r"((b)[0]), "r"((b)[1]))

// ─────────────── globals ───────────────
static __device__ float  g_c2[1024];
static __device__ int    g_maxcBits;
static __device__ float  g_accum[2];          // [0]=sum m*||z-q||^2, [1]=sum m
static __device__ int    g_fbCount;
static __device__ int    g_fbTok[32768];
static __device__ float  g_fbV[32768];
static __device__ int    g_fbIdx[32768 * 24];
static __device__ int    g_fb2Count;
static __device__ int    g_fb2Tok[32768];
static __device__ int    g_fb2Done;
static __device__ __half g_zh[32768 * 256];   // fp16 copy of z
static __device__ __half g_ch[1024 * 256];    // fp16 copy of codebook

// ───── fused prep: z/cb fp16 conversion + ||c||^2 + global init ─────
// grid = 4224: blocks [0,4096) convert z; blocks [4096,4224) handle cb.
__global__ void k_prep(const float4* __restrict__ z, const float4* __restrict__ cb) {
    const int tid = threadIdx.x;
    if (blockIdx.x < 4096) {
        const size_t i = (size_t)blockIdx.x * 256 + tid;
        float4 a = z[i * 2], b = z[i * 2 + 1];
        __half2 h0 = __floats2half2_rn(a.x, a.y);
        __half2 h1 = __floats2half2_rn(a.z, a.w);
        __half2 h2 = __floats2half2_rn(b.x, b.y);
        __half2 h3 = __floats2half2_rn(b.z, b.w);
        uint4 o;
        o.x = *(uint32_t*)&h0; o.y = *(uint32_t*)&h1;
        o.z = *(uint32_t*)&h2; o.w = *(uint32_t*)&h3;
        ((uint4*)g_zh)[i] = o;
        return;
    }
    const int cbid = blockIdx.x - 4096;       // 0..127
    if (cbid == 0 && tid == 0) {
        g_accum[0] = 0.0f; g_accum[1] = 0.0f;
        g_maxcBits = 0; g_fbCount = 0; g_fb2Count = 0; g_fb2Done = 0;
    }
    {   // convert codebook slice
        const size_t i = (size_t)cbid * 256 + tid;
        float4 a = cb[i * 2], b = cb[i * 2 + 1];
        __half2 h0 = __floats2half2_rn(a.x, a.y);
        __half2 h1 = __floats2half2_rn(a.z, a.w);
        __half2 h2 = __floats2half2_rn(b.x, b.y);
        __half2 h3 = __floats2half2_rn(b.z, b.w);
        uint4 o;
        o.x = *(uint32_t*)&h0; o.y = *(uint32_t*)&h1;
        o.z = *(uint32_t*)&h2; o.w = *(uint32_t*)&h3;
        ((uint4*)g_ch)[i] = o;
    }
    {   // ||c||^2: warp per code, 8 codes per block
        int k    = cbid * 8 + (tid >> 5);
        int lane = tid & 31;
        float4 a = cb[(size_t)k * 64 + lane];
        float4 b = cb[(size_t)k * 64 + 32 + lane];
        float s = a.x*a.x + a.y*a.y + a.z*a.z + a.w*a.w
                + b.x*b.x + b.y*b.y + b.z*b.z + b.w*b.w;
        #pragma unroll
        for (int o = 16; o; o >>= 1) s += __shfl_down_sync(0xffffffffu, s, o);
        if (lane == 0) {
            g_c2[k] = s;
            atomicMax(&g_maxcBits, __float_as_int(sqrtf(s)));
        }
    }
}

// ───── fused fp16 GEMM (ldmatrix) + top-3 + certified select + STE epilogue ─────
static constexpr int ROW_B   = 144;                 // bytes per smem row (64 halves + pad)
static constexpr int T_CHUNK = 128 * ROW_B;         // 18432 B per tile
static constexpr int OFF_A0 = 0;
static constexpr int OFF_A1 = T_CHUNK;
static constexpr int OFF_B0 = 2 * T_CHUNK;
static constexpr int OFF_B1 = 3 * T_CHUNK;
static constexpr int DYN_SMEM = 4 * T_CHUNK;        // 73728 B -> 2 CTAs/SM

extern __shared__ char dynsmem[];

__device__ __forceinline__ void fill_chunk(uint32_t sbase, int it, int mtile, int tid) {
    const int nt = it >> 2, kc = it & 3;
    const uint32_t bufA = sbase + ((it & 1) ? OFF_A1 : OFF_A0);
    const uint32_t bufB = sbase + ((it & 1) ? OFF_B1 : OFF_B0);
    const __half* zsrc = g_zh + (size_t)mtile * 128 * 256 + kc * 64;
    const __half* bsrc = g_ch + (size_t)nt    * 128 * 256 + kc * 64;
    #pragma unroll
    for (int i = 0; i < 4; i++) {
        int u = tid + i * 256, row = u >> 3, q = u & 7;
        CP_ASYNC16(bufA + row * ROW_B + q * 16, zsrc + (size_t)row * 256 + q * 8);
        CP_ASYNC16(bufB + row * ROW_B + q * 16, bsrc + (size_t)row * 256 + q * 8);
    }
}

__global__ void __launch_bounds__(256, 2) k_mma(const float* __restrict__ z,
                                                const float* __restrict__ mask,
                                                const float* __restrict__ cb,
                                                float* __restrict__ outQ,
                                                float* __restrict__ outIdx) {
    __shared__ float c2sh[1024];
    __shared__ float znsh[128];
    __shared__ int   idxsh[128];
    __shared__ float mks[128];
    __shared__ float lossP[8], maskP[8];

    const int tid  = threadIdx.x;
    const int wid  = tid >> 5;
    const int lane = tid & 31;
    const int g    = lane >> 2;
    const int tg   = lane & 3;
    const int mw   = wid >> 1;
    const int nw   = wid & 1;
    const int mtile = blockIdx.x;

    uint32_t sbase = smem_u32(dynsmem);

    const int sub = lane >> 3, rr = lane & 7;
    uint32_t aoff[2], boff[4];
    #pragma unroll
    for (int mt = 0; mt < 2; mt++)
        aoff[mt] = (uint32_t)((mw * 32 + mt * 16 + (sub & 1) * 8 + rr) * ROW_B
                              + (sub >> 1) * 16);
    #pragma unroll
    for (int p2 = 0; p2 < 4; p2++)
        boff[p2] = (uint32_t)((nw * 64 + p2 * 16 + (sub >> 1) * 8 + rr) * ROW_B
                              + (sub & 1) * 16);

    #pragma unroll
    for (int i = 0; i < 4; i++) c2sh[tid + i * 256] = g_c2[tid + i * 256];

    float b1[4], b2[4], b3[4]; int i1[4], i2[4], i3[4];
    #pragma unroll
    for (int s = 0; s < 4; s++) {
        b1[s] = 3.0e38f; b2[s] = 3.0e38f; b3[s] = 3.0e38f;
        i1[s] = 0; i2[s] = 0; i3[s] = 0;
    }

    float acc[2][8][4];

    fill_chunk(sbase, 0, mtile, tid);
    CP_COMMIT();

    for (int it = 0; it < 32; it++) {
        const int kc = it & 3;
        const int nt = it >> 2;
        const uint32_t bufA = sbase + ((it & 1) ? OFF_A1 : OFF_A0);
        const uint32_t bufB = sbase + ((it & 1) ? OFF_B1 : OFF_B0);

        CP_WAIT0();
        __syncthreads();
        if (it + 1 < 32) { fill_chunk(sbase, it + 1, mtile, tid); CP_COMMIT(); }

        if (kc == 0) {
            #pragma unroll
            for (int mt = 0; mt < 2; mt++)
                #pragma unroll
                for (int ntl = 0; ntl < 8; ntl++)
                    #pragma unroll
                    for (int r = 0; r < 4; r++) acc[mt][ntl][r] = 0.0f;
        }

        #pragma unroll
        for (int ks = 0; ks < 4; ks++) {
            const uint32_t kb = ks * 32;
            uint32_t af[2][4], bf[8][2];
            #pragma unroll
            for (int mt = 0; mt < 2; mt++)
                LDMATRIX_X4(af[mt][0], af[mt][1], af[mt][2], af[mt][3],
                            bufA + aoff[mt] + kb);
            #pragma unroll
            for (int p2 = 0; p2 < 4; p2++)
                LDMATRIX_X4(bf[2 * p2][0], bf[2 * p2][1],
                            bf[2 * p2 + 1][0], bf[2 * p2 + 1][1],
                            bufB + boff[p2] + kb);
            #pragma unroll
            for (int mt = 0; mt < 2; mt++)
                #pragma unroll
                for (int ntl = 0; ntl < 8; ntl++)
                    MMA_FP16(acc[mt][ntl], af[mt], bf[ntl]);
        }

        if (kc == 3) {
            #pragma unroll
            for (int mt = 0; mt < 2; mt++) {
                #pragma unroll
                for (int half = 0; half < 2; half++) {
                    const int slot = mt * 2 + half;
                    #pragma unroll
                    for (int ntl = 0; ntl < 8; ntl++) {
                        const int c0 = nt * 128 + nw * 64 + ntl * 8 + tg * 2;
                        #pragma unroll
                        for (int cc = 0; cc < 2; cc++) {
                            float s = fmaf(-2.0f, acc[mt][ntl][half * 2 + cc], c2sh[c0 + cc]);
                            if (s < b3[slot]) {
                                if (s < b2[slot]) {
                                    b3[slot] = b2[slot]; i3[slot] = i2[slot];
                                    if (s < b1[slot]) {
                                        b2[slot] = b1[slot]; i2[slot] = i1[slot];
                                        b1[slot] = s;        i1[slot] = c0 + cc;
                                    } else { b2[slot] = s; i2[slot] = c0 + cc; }
                                } else { b3[slot] = s; i3[slot] = c0 + cc; }
                            }
                        }
                    }
                }
            }
        }
    }

    // ───── fused epilogue (tier 1 only) ─────
    __syncthreads();
    float* sS = (float*)dynsmem;                // [128][24] candidate scores
    int*   sI = (int*)(dynsmem + 128 * 24 * 4); // [128][24] candidate indices

    #pragma unroll
    for (int slot = 0; slot < 4; slot++) {
        const int row = mw * 32 + (slot >> 1) * 16 + (slot & 1) * 8 + g;
        const int col = (nw * 4 + tg) * 3;
        sS[row * 24 + col]     = b1[slot]; sI[row * 24 + col]     = i1[slot];
        sS[row * 24 + col + 1] = b2[slot]; sI[row * 24 + col + 1] = i2[slot];
        sS[row * 24 + col + 2] = b3[slot]; sI[row * 24 + col + 2] = i3[slot];
    }

    #pragma unroll 1
    for (int t = 0; t < 16; t++) {
        const int row = wid * 16 + t;
        const float4* z4 = (const float4*)(z + (size_t)(mtile * 128 + row) * 256) + lane * 2;
        float4 a0 = z4[0], a1 = z4[1];
        float s = a0.x*a0.x + a0.y*a0.y + a0.z*a0.z + a0.w*a0.w
                + a1.x*a1.x + a1.y*a1.y + a1.z*a1.z + a1.w*a1.w;
        #pragma unroll
        for (int o = 16; o; o >>= 1) s += __shfl_down_sync(0xffffffffu, s, o);
        if (lane == 0) znsh[row] = s;
    }
    __syncthreads();

    if (tid < 128) {
        const int token = mtile * 128 + tid;
        const float m = mask[token];
        mks[tid] = m;
        float s1 = 3.0e38f, s2 = 3.0e38f, v = 3.0e38f;
        int idx1 = 0x7fffffff;
        #pragma unroll 4
        for (int j = 0; j < 24; j++) {
            float s = sS[tid * 24 + j];
            int   i = sI[tid * 24 + j];
            if (s < s1 || (s == s1 && i < idx1)) { s2 = s1; s1 = s; idx1 = i; }
            else s2 = fminf(s2, s);
            if ((j % 3) == 2) v = fminf(v, s);
        }
        const float maxc = __int_as_float(g_maxcBits);
        const float delta = 1.1e-3f * sqrtf(znsh[tid]) * maxc + 3e-2f;
        if (s2 - s1 > 2.0f * delta) {
            idxsh[tid] = idx1;
            outIdx[token] = (m > 0.0f) ? (float)idx1 : 0.0f;
        } else {
            idxsh[tid] = -1;
            int pos = atomicAdd(&g_fbCount, 1);
            g_fbTok[pos] = token;
            g_fbV[pos]   = v;
            #pragma unroll 4
            for (int j = 0; j < 24; j++) g_fbIdx[(size_t)pos * 24 + j] = sI[tid * 24 + j];
        }
    }
    __syncthreads();

    float lsum = 0.0f, msum = 0.0f;
    #pragma unroll 1
    for (int t = 0; t < 16; t++) {
        const int row = wid * 16 + t;
        const int idx = idxsh[row];
        if (idx < 0) continue;
        const int token = mtile * 128 + row;
        const float m = mks[row];
        const float4* z4 = (const float4*)(z  + (size_t)token * 256) + lane * 2;
        const float4* q4 = (const float4*)(cb + (size_t)idx   * 256) + lane * 2;
        float4 za = z4[0], zb = z4[1];
        float4 qa = q4[0], qb = q4[1];
        float ss = 0.0f;
        {
            float dx = za.x - qa.x, dy = za.y - qa.y, dz = za.z - qa.z, dw = za.w - qa.w;
            ss += dx*dx + dy*dy + dz*dz + dw*dw;
            dx = zb.x - qb.x; dy = zb.y - qb.y; dz = zb.z - qb.z; dw = zb.w - qb.w;
            ss += dx*dx + dy*dy + dz*dz + dw*dw;
        }
        float4* o4 = (float4*)(outQ + (size_t)token * 256) + lane * 2;
        float4 oa, ob;
        oa.x = (za.x + (qa.x - za.x)) * m; oa.y = (za.y + (qa.y - za.y)) * m;
        oa.z = (za.z + (qa.z - za.z)) * m; oa.w = (za.w + (qa.w - za.w)) * m;
        ob.x = (zb.x + (qb.x - zb.x)) * m; ob.y = (zb.y + (qb.y - zb.y)) * m;
        ob.z = (zb.z + (qb.z - zb.z)) * m; ob.w = (zb.w + (qb.w - zb.w)) * m;
        o4[0] = oa; o4[1] = ob;
        lsum += ss * m;
        if (lane == 0) msum += m;
    }
    #pragma unroll
    for (int o = 16; o; o >>= 1) lsum += __shfl_down_sync(0xffffffffu, lsum, o);
    if (lane == 0) { lossP[wid] = lsum; maskP[wid] = msum; }
    __syncthreads();
    if (tid == 0) {
        float a = 0.0f, b = 0.0f;
        #pragma unroll
        for (int w = 0; w < 8; w++) { a += lossP[w]; b += maskP[w]; }
        atomicAdd(&g_accum[0], a);
        atomicAdd(&g_accum[1], b);
    }
}

// ───── fb1: batched exact recheck of 24 candidates; unresolved -> fb2 list ─────
__global__ void k_fb1(const float* __restrict__ z,
                      const float* __restrict__ mask,
                      const float* __restrict__ cb,
                      float* __restrict__ outQ,
                      float* __restrict__ outIdx) {
    const int warp = threadIdx.x >> 5;
    const int lane = threadIdx.x & 31;
    const int wglobal = blockIdx.x * 8 + warp;
    const int nwarps  = gridDim.x * 8;
    const int count = g_fbCount;
    const float maxc = __int_as_float(g_maxcBits);

    for (int i = wglobal; i < count; i += nwarps) {
        const int token = g_fbTok[i];
        const float v   = g_fbV[i];

        const float4* z4 = (const float4*)(z + (size_t)token * 256) + lane * 2;
        const float4 za = z4[0], zb = z4[1];
        float zn = za.x*za.x + za.y*za.y + za.z*za.z + za.w*za.w
                 + zb.x*zb.x + zb.y*zb.y + zb.z*zb.z + zb.w*zb.w;
        #pragma unroll
        for (int o = 16; o; o >>= 1) zn += __shfl_xor_sync(0xffffffffu, zn, o);
        const float delta = 1.1e-3f * sqrtf(zn) * maxc + 3e-2f;

        float bS = 3.0e38f; int bI = 0x7fffffff;
        #pragma unroll 1
        for (int b = 0; b < 3; b++) {
            float d[8]; int ix[8];
            #pragma unroll
            for (int cc = 0; cc < 8; cc++) {
                ix[cc] = g_fbIdx[(size_t)i * 24 + b * 8 + cc];
                const float4* c4 = (const float4*)(cb + (size_t)ix[cc] * 256) + lane * 2;
                float4 xa = c4[0], xb = c4[1];
                d[cc] = za.x*xa.x + za.y*xa.y + za.z*xa.z + za.w*xa.w
                      + zb.x*xb.x + zb.y*xb.y + zb.z*xb.z + zb.w*xb.w;
            }
            #pragma unroll
            for (int o = 16; o; o >>= 1) {
                #pragma unroll
                for (int cc = 0; cc < 8; cc++)
                    d[cc] += __shfl_xor_sync(0xffffffffu, d[cc], o);
            }
            #pragma unroll
            for (int cc = 0; cc < 8; cc++) {
                float s = fmaf(-2.0f, d[cc], g_c2[ix[cc]]);
                if (s < bS || (s == bS && ix[cc] < bI)) { bS = s; bI = ix[cc]; }
            }
        }

        if (bS < v - delta) {
            const int idx = bI;
            const float m = mask[token];
            const float4* q4 = (const float4*)(cb + (size_t)idx * 256) + lane * 2;
            float4 qa = q4[0], qb = q4[1];
            float ss = 0.0f;
            {
                float dx = za.x - qa.x, dy = za.y - qa.y, dz = za.z - qa.z, dw = za.w - qa.w;
                ss += dx*dx + dy*dy + dz*dz + dw*dw;
                dx = zb.x - qb.x; dy = zb.y - qb.y; dz = zb.z - qb.z; dw = zb.w - qb.w;
                ss += dx*dx + dy*dy + dz*dz + dw*dw;
            }
            float4* o4 = (float4*)(outQ + (size_t)token * 256) + lane * 2;
            float4 oa, ob;
            oa.x = (za.x + (qa.x - za.x)) * m; oa.y = (za.y + (qa.y - za.y)) * m;
            oa.z = (za.z + (qa.z - za.z)) * m; oa.w = (za.w + (qa.w - za.w)) * m;
            ob.x = (zb.x + (qb.x - zb.x)) * m; ob.y = (zb.y + (qb.y - zb.y)) * m;
            ob.z = (zb.z + (qb.z - zb.z)) * m; ob.w = (zb.w + (qb.w - zb.w)) * m;
            o4[0] = oa; o4[1] = ob;
            #pragma unroll
            for (int o = 16; o; o >>= 1) ss += __shfl_down_sync(0xffffffffu, ss, o);
            if (lane == 0) {
                outIdx[token] = (m > 0.0f) ? (float)idx : 0.0f;
                atomicAdd(&g_accum[0], ss * m);
                atomicAdd(&g_accum[1], m);
            }
        } else if (lane == 0) {
            g_fb2Tok[atomicAdd(&g_fb2Count, 1)] = token;
        }
    }
}

// ───── fb2: block-per-token full scan + last-block loss finalize ─────
__global__ void k_fb2(const float* __restrict__ z,
                      const float* __restrict__ mask,
                      const float* __restrict__ cb,
                      float* __restrict__ outQ,
                      float* __restrict__ outIdx,
                      float* __restrict__ outLoss) {
    __shared__ float wS[8];
    __shared__ int   wI[8];
    __shared__ int   sIdx;
    const int tid  = threadIdx.x;
    const int wid  = tid >> 5;
    const int lane = tid & 31;
    const int count = g_fb2Count;

    for (int t = blockIdx.x; t < count; t += gridDim.x) {
        const int token = g_fb2Tok[t];
        const float4* z4 = (const float4*)(z + (size_t)token * 256) + lane * 2;
        const float4 za = z4[0], zb = z4[1];

        float bS = 3.0e38f; int bI = 0x7fffffff;
        #pragma unroll 1
        for (int b = 0; b < 16; b++) {
            const int c0 = wid * 128 + b * 8;
            float d[8];
            #pragma unroll
            for (int cc = 0; cc < 8; cc++) {
                const float4* c4 = (const float4*)(cb + (size_t)(c0 + cc) * 256) + lane * 2;
                float4 xa = c4[0], xb = c4[1];
                d[cc] = za.x*xa.x + za.y*xa.y + za.z*xa.z + za.w*xa.w
                      + zb.x*xb.x + zb.y*xb.y + zb.z*xb.z + zb.w*xb.w;
            }
            #pragma unroll
            for (int o = 16; o; o >>= 1) {
                #pragma unroll
                for (int cc = 0; cc < 8; cc++)
                    d[cc] += __shfl_xor_sync(0xffffffffu, d[cc], o);
            }
            #pragma unroll
            for (int cc = 0; cc < 8; cc++) {
                float s = fmaf(-2.0f, d[cc], g_c2[c0 + cc]);
                if (s < bS || (s == bS && (c0 + cc) < bI)) { bS = s; bI = c0 + cc; }
            }
        }
        if (lane == 0) { wS[wid] = bS; wI[wid] = bI; }
        __syncthreads();
        if (tid == 0) {
            float fS = wS[0]; int fI = wI[0];
            #pragma unroll
            for (int w = 1; w < 8; w++)
                if (wS[w] < fS || (wS[w] == fS && wI[w] < fI)) { fS = wS[w]; fI = wI[w]; }
            sIdx = fI;
        }
        __syncthreads();

        if (wid == 0) {
            const int idx = sIdx;
            const float m = mask[token];
            const float4* q4 = (const float4*)(cb + (size_t)idx * 256) + lane * 2;
            float4 qa = q4[0], qb = q4[1];
            float ss = 0.0f;
            {
                float dx = za.x - qa.x, dy = za.y - qa.y, dz = za.z - qa.z, dw = za.w - qa.w;
                ss += dx*dx + dy*dy + dz*dz + dw*dw;
                dx = zb.x - qb.x; dy = zb.y - qb.y; dz = zb.z - qb.z; dw = zb.w - qb.w;
                ss += dx*dx + dy*dy + dz*dz + dw*dw;
            }
            float4* o4 = (float4*)(outQ + (size_t)token * 256) + lane * 2;
            float4 oa, ob;
            oa.x = (za.x + (qa.x - za.x)) * m; oa.y = (za.y + (qa.y - za.y)) * m;
            oa.z = (za.z + (qa.z - za.z)) * m; oa.w = (za.w + (qa.w - za.w)) * m;
            ob.x = (zb.x + (qb.x - zb.x)) * m; ob.y = (zb.y + (qb.y - zb.y)) * m;
            ob.z = (zb.z + (qb.z - zb.z)) * m; ob.w = (zb.w + (qb.w - zb.w)) * m;
            o4[0] = oa; o4[1] = ob;
            #pragma unroll
            for (int o = 16; o; o >>= 1) ss += __shfl_down_sync(0xffffffffu, ss, o);
            if (lane == 0) {
                outIdx[token] = (m > 0.0f) ? (float)idx : 0.0f;
                atomicAdd(&g_accum[0], ss * m);
                atomicAdd(&g_accum[1], m);
            }
        }
        __syncthreads();
    }

    // last-done block writes the loss (all g_accum adds complete & fenced)
    if (tid == 0) {
        __threadfence();
        int done = atomicAdd(&g_fb2Done, 1);
        if (done == (int)gridDim.x - 1) {
            outLoss[0] = 0.25f * (g_accum[0] / (g_accum[1] * 256.0f));
        }
    }
}

// ─────────────── launcher ───────────────
extern "C" void kernel_launch(void* const* d_in, const int* in_sizes, int n_in,
                              void* d_out, int out_size) {
    const float* z    = (const float*)d_in[0];   // (B,S,D)
    const float* mask = (const float*)d_in[1];   // (B,S)
    const float* cb   = (const float*)d_in[2];   // (K,D)

    const int BSD = in_sizes[0];                 // 8388608
    const int N   = in_sizes[1];                 // 32768

    float* out     = (float*)d_out;
    float* outQ    = out;
    float* outLoss = out + BSD;
    float* outIdx  = out + BSD + 1;

    cudaFuncSetAttribute(k_mma, cudaFuncAttributeMaxDynamicSharedMemorySize, DYN_SMEM);

    k_prep<<<4224, 256>>>((const float4*)z, (const float4*)cb);
    k_mma<<<N / 128, 256, DYN_SMEM>>>(z, mask, cb, outQ, outIdx);
    k_fb1<<<512, 256>>>(z, mask, cb, outQ, outIdx);
    k_fb2<<<192, 256>>>(z, mask, cb, outQ, outIdx, outLoss);
}